// round 16
// baseline (speedup 1.0000x reference)
#include <cuda_runtime.h>
#include <math.h>
#include <stdint.h>

// BackflowNet: B=128, N=64, D=2, H=64, M=64, L=2.
// R16 = R15 + quarter-granularity pass grid (512 CTAs, launch_bounds(128,2),
// NO reg cap) to fix the 256-CTA wave imbalance (40 of 148 SMs half-idle).
//   k_wfuse -> k_node -> k_passA(512) -> k_agg0(128) -> k_passB(512) -> k_final(128)

__device__ float g_hid0[128u*64u*64u*64u];  // [b][i][j][m] hidden0 (post-gelu)
__device__ float g_hv [128u*64u*64u];       // hv
__device__ float g_pre[128u*64u*64u];       // pre
__device__ float g_accp0[512u*4096u];       // passA partials per (b,quarter)
__device__ float g_accp1[512u*4096u];       // passB partials
__device__ float g_Wf[4*4096];              // W_A..W_D fused products
__device__ float g_bf[4*64];                // fused bias rows

__device__ __forceinline__ float gelu_exact(float x) {
    return 0.5f * x * (1.0f + erff(x * 0.70710678118654752f));
}
__device__ __forceinline__ unsigned long long pk2(float lo, float hi) {
    unsigned long long r;
    asm("mov.b64 %0, {%1, %2};" : "=l"(r) : "f"(lo), "f"(hi));
    return r;
}
__device__ __forceinline__ void upk2(unsigned long long v, float& lo, float& hi) {
    asm("mov.b64 {%0, %1}, %2;" : "=f"(lo), "=f"(hi) : "l"(v));
}
__device__ __forceinline__ void fma2(unsigned long long& d, unsigned long long a, unsigned long long b) {
    asm("fma.rn.f32x2 %0, %1, %2, %0;" : "+l"(d) : "l"(a), "l"(b));
}

#define RANK1(rr, av, wv) \
    rr[0]=fmaf(av, wv.x, rr[0]); rr[1]=fmaf(av, wv.y, rr[1]); \
    rr[2]=fmaf(av, wv.z, rr[2]); rr[3]=fmaf(av, wv.w, rr[3]);
#define TILE4(R, a0v, a1v, a2v, a3v, W) \
    RANK1(R[0], a0v, W) RANK1(R[1], a1v, W) RANK1(R[2], a2v, W) RANK1(R[3], a3v, W)

// scalar 64x64x64 GEMM (256 threads) for small per-batch stages
__device__ __forceinline__ void mm64(
    const float* __restrict__ in, int istride,
    const float* __restrict__ w, const float* __restrict__ bias,
    float* __restrict__ out, int ostride,
    int act, float inscale, bool accum, int tid)
{
    const int mb = (tid & 15) * 4;
    const int jb = (tid >> 4) * 4;
    const float* i0 = in + jb * istride;
    const float* i1 = i0 + istride;
    const float* i2 = i1 + istride;
    const float* i3 = i2 + istride;
    float r[4][4] = {};
    #pragma unroll 4
    for (int k = 0; k < 64; k += 4) {
        float4 w0 = *(const float4*)(w + (k + 0) * 64 + mb);
        float4 w1 = *(const float4*)(w + (k + 1) * 64 + mb);
        float4 w2 = *(const float4*)(w + (k + 2) * 64 + mb);
        float4 w3 = *(const float4*)(w + (k + 3) * 64 + mb);
        float4 a0 = *(const float4*)(i0 + k);
        float4 a1 = *(const float4*)(i1 + k);
        float4 a2 = *(const float4*)(i2 + k);
        float4 a3 = *(const float4*)(i3 + k);
        TILE4(r, a0.x, a1.x, a2.x, a3.x, w0)
        TILE4(r, a0.y, a1.y, a2.y, a3.y, w1)
        TILE4(r, a0.z, a1.z, a2.z, a3.z, w2)
        TILE4(r, a0.w, a1.w, a2.w, a3.w, w3)
    }
    #pragma unroll
    for (int u = 0; u < 4; u++) {
        float badd = bias ? bias[mb + u] : 0.f;
        #pragma unroll
        for (int v = 0; v < 4; v++) {
            float val = fmaf(r[v][u], inscale, badd);
            if (act == 1) val = gelu_exact(val);
            else if (act == 2) val = tanhf(val);
            float* o = out + (jb + v) * ostride + mb + u;
            if (accum) *o += val; else *o = val;
        }
    }
}

// 64x64x64 f32x2 GEMM tile, 64 threads, 8x8/thread, gelu epilogue.
// MODE 0: [pre-sync if PRESYNC]; write outT (stride 68) [+gout stride 64]; post-sync.
// MODE 1: masked accumulate into accR (row jb+r != maski), no syncs.
template<int MODE, int PRESYNC>
__device__ __forceinline__ void tile_gemm(
    const float* Ab, int astr, const float* __restrict__ Ws,
    int jb, int mb, const float badd[8],
    float* outT, float* gout, float (*accR)[8], int maski)
{
    unsigned long long A[8][4];
    #pragma unroll
    for (int r = 0; r < 8; r++)
        #pragma unroll
        for (int p = 0; p < 4; p++) A[r][p] = 0ull;
    const float* base = Ab + jb * astr;
    #pragma unroll 2
    for (int k = 0; k < 64; k += 4) {
        float4 av[8];
        #pragma unroll
        for (int r = 0; r < 8; r++) av[r] = *(const float4*)(base + r * astr + k);
        #pragma unroll
        for (int kk = 0; kk < 4; kk++) {
            ulonglong2 wlo = *(const ulonglong2*)(Ws + (k + kk) * 64 + mb);
            ulonglong2 whi = *(const ulonglong2*)(Ws + (k + kk) * 64 + mb + 4);
            #pragma unroll
            for (int r = 0; r < 8; r++) {
                float a = (kk == 0) ? av[r].x : (kk == 1) ? av[r].y
                        : (kk == 2) ? av[r].z : av[r].w;
                unsigned long long ab = pk2(a, a);
                fma2(A[r][0], ab, wlo.x);
                fma2(A[r][1], ab, wlo.y);
                fma2(A[r][2], ab, whi.x);
                fma2(A[r][3], ab, whi.y);
            }
        }
    }
    if (MODE == 0) {
        if (PRESYNC) __syncthreads();
        #pragma unroll
        for (int r = 0; r < 8; r++) {
            float o[8];
            #pragma unroll
            for (int p = 0; p < 4; p++) {
                float lo, hi;
                upk2(A[r][p], lo, hi);
                o[2 * p]     = gelu_exact(lo + badd[2 * p]);
                o[2 * p + 1] = gelu_exact(hi + badd[2 * p + 1]);
            }
            float4 lo4 = make_float4(o[0], o[1], o[2], o[3]);
            float4 hi4 = make_float4(o[4], o[5], o[6], o[7]);
            *(float4*)(outT + (jb + r) * 68 + mb)     = lo4;
            *(float4*)(outT + (jb + r) * 68 + mb + 4) = hi4;
            if (gout) {
                *(float4*)(gout + (jb + r) * 64 + mb)     = lo4;
                *(float4*)(gout + (jb + r) * 64 + mb + 4) = hi4;
            }
        }
        __syncthreads();
    } else {
        #pragma unroll
        for (int r = 0; r < 8; r++) {
            if (jb + r != maski) {
                #pragma unroll
                for (int p = 0; p < 4; p++) {
                    float lo, hi;
                    upk2(A[r][p], lo, hi);
                    accR[r][2 * p]     += gelu_exact(lo + badd[2 * p]);
                    accR[r][2 * p + 1] += gelu_exact(hi + badd[2 * p + 1]);
                }
            }
        }
    }
}

// ---- fused weight products ----
__global__ void __launch_bounds__(256)
k_wfuse(const float* __restrict__ ew2, const float* __restrict__ eb2,
        const float* __restrict__ vw1, const float* __restrict__ vw2,
        const float* __restrict__ vb2,
        const float* __restrict__ cw1, const float* __restrict__ cb1)
{
    __shared__ float sL[4096], sR[4096];
    const int s = blockIdx.x, tid = threadIdx.x;
    const float *L, *R, *bL, *extra = 0;
    if (s == 0)      { L = ew2;        R = vw1 + 4096;         bL = eb2; }
    else if (s == 1) { L = vw2;        R = cw1;                bL = vb2; extra = cb1; }
    else if (s == 2) { L = vw2;        R = vw1 + 8192 + 4096;  bL = vb2; }
    else             { L = vw2 + 4096; R = cw1 + 4096;         bL = vb2 + 64; extra = cb1 + 64; }
    for (int t = tid; t < 4096; t += 256) { sL[t] = L[t]; sR[t] = R[t]; }
    __syncthreads();
    mm64(sL, 64, sR, 0, g_Wf + s * 4096, 64, 0, 1.f, false, tid);
    if (tid < 64) {
        float acc = extra ? extra[tid] : 0.f;
        #pragma unroll 4
        for (int k = 0; k < 64; k++) acc = fmaf(bL[k], sR[k * 64 + tid], acc);
        g_bf[s * 64 + tid] = acc;
    }
}

// ---- node MLP: hv0 + pre0 ----
__global__ void __launch_bounds__(256)
k_node(const float* __restrict__ x, const float* __restrict__ spin,
       const float* __restrict__ nw1, const float* __restrict__ nb1,
       const float* __restrict__ nw2, const float* __restrict__ nb2,
       const float* __restrict__ vw1, const float* __restrict__ vb1)
{
    extern __shared__ float nsm[];
    float* sW = nsm; float* sA = nsm + 4096; float* sB = nsm + 8192;
    float* sxs = nsm + 12288; float* ssp = nsm + 12416; float* sw1 = nsm + 12480;
    const int b = blockIdx.x, tid = threadIdx.x;
    if (tid < 128) sxs[tid] = x[b * 128 + tid];
    if (tid < 64)  ssp[tid] = spin[b * 64 + tid];
    if (tid < 192) sw1[tid] = nw1[tid];
    for (int t = tid; t < 4096; t += 256) sW[t] = nw2[t];
    __syncthreads();
    for (int t = tid; t < 4096; t += 256) {
        int i = t >> 6, h = t & 63;
        float v = fmaf(sxs[i * 2], sw1[h],
                  fmaf(sxs[i * 2 + 1], sw1[64 + h],
                  fmaf(ssp[i], sw1[128 + h], nb1[h])));
        sA[t] = gelu_exact(v);
    }
    __syncthreads();
    mm64(sA, 64, sW, nb2, sB, 64, 0, 1.f, false, tid);   // hv0
    __syncthreads();
    for (int t = tid; t < 4096; t += 256) { g_hv[b * 4096 + t] = sB[t]; sW[t] = vw1[t]; }
    __syncthreads();
    mm64(sB, 64, sW, vb1, sA, 64, 0, 1.f, false, tid);   // pre0
    __syncthreads();
    for (int t = tid; t < 4096; t += 256) g_pre[b * 4096 + t] = sA[t];
}

// ---- pass A: edgeMLP -> hidden0 (store) -> gv0 (masked acc), (b,quarter) ----
#define PA_T0   0        // 2 x [64][68]
#define PA_WA   8704
#define PA_WB   12800
#define PA_PRE  16896    // [16][64]
#define PA_F4   17920    // [2][64][4]
#define PA_XS   18432
#define PA_EW1  18560    // [4][64]
#define PA_BEB1 18816
#define PA_BFA  18880
#define PA_BB   18944
#define PA_FLOATS 19008
#define PA_BYTES (PA_FLOATS * 4)

__global__ void __launch_bounds__(128, 2)
k_passA(const float* __restrict__ x, const float* __restrict__ ew1,
        const float* __restrict__ eb1)
{
    extern __shared__ float sa[];
    const int tid = threadIdx.x;
    const int unit = tid >> 6, t64 = tid & 63;
    const int mb = (t64 & 7) * 8, jb = (t64 >> 3) * 8;
    const int b = blockIdx.x >> 2, q = blockIdx.x & 3;
    float* T    = sa + PA_T0 + unit * 4352;
    float* WA   = sa + PA_WA;
    float* WB   = sa + PA_WB;
    float* PRE  = sa + PA_PRE;
    float* F4u  = sa + PA_F4 + unit * 256;
    float* XS   = sa + PA_XS;
    float* EW1  = sa + PA_EW1;
    float* BEB1 = sa + PA_BEB1;
    float* BFA  = sa + PA_BFA;
    float* BB   = sa + PA_BB;

    for (int t = tid; t < 4096; t += 128) { WA[t] = g_Wf[t]; WB[t] = g_Wf[4096 + t]; }
    for (int t = tid; t < 1024; t += 128) PRE[t] = g_pre[b * 4096 + q * 1024 + t];
    if (tid < 128) XS[tid] = x[b * 128 + tid];
    if (tid < 64) {
        EW1[tid] = ew1[tid]; EW1[64 + tid] = ew1[64 + tid];
        EW1[128 + tid] = ew1[128 + tid]; EW1[192 + tid] = ew1[192 + tid];
        BEB1[tid] = eb1[tid]; BFA[tid] = g_bf[tid]; BB[tid] = g_bf[64 + tid];
    }
    __syncthreads();

    float accR[8][8] = {};
    float badd[8];
    for (int iq = 0; iq < 8; iq++) {
        const int il = iq * 2 + unit;
        const int i = q * 16 + il;
        {   // geometry for this unit's source row
            int j = t64;
            float d0 = XS[j * 2]     - XS[i * 2];
            float d1 = XS[j * 2 + 1] - XS[i * 2 + 1];
            float r2 = d0 * d0 + d1 * d1;
            float rr = sqrtf(r2 + 1e-12f);
            *(float4*)(F4u + j * 4) = make_float4(d0, d1, rr, r2);
        }
        // this sync also guards prior-iq gv0 readers of T before edge overwrite
        __syncthreads();
        {   // edge MLP hidden: thread owns column m
            int m = t64;
            float w0 = EW1[m], w1 = EW1[64 + m], w2 = EW1[128 + m], w3 = EW1[192 + m];
            float bb = BEB1[m];
            #pragma unroll 4
            for (int j = 0; j < 64; j++) {
                const float* f = F4u + j * 4;
                float v = fmaf(f[0], w0, fmaf(f[1], w1, fmaf(f[2], w2, fmaf(f[3], w3, bb))));
                T[j * 68 + m] = gelu_exact(v);
            }
        }
        __syncthreads();
        // hidden0 = gelu(edge_hidden @ W_A + bA + pre0[i])  [store to global]
        #pragma unroll
        for (int u = 0; u < 8; u++) badd[u] = PRE[il * 64 + mb + u] + BFA[mb + u];
        tile_gemm<0, 1>(T, 68, WA, jb, mb, badd, T,
                        g_hid0 + (size_t)(b * 64 + i) * 4096, 0, -1);
        // gv0 = gelu(hidden0 @ W_B + bB), masked acc
        #pragma unroll
        for (int u = 0; u < 8; u++) badd[u] = BB[mb + u];
        tile_gemm<1, 0>(T, 68, WB, jb, mb, badd, 0, 0, accR, i);
    }
    __syncthreads();
    // combine unit accumulators -> g_accp0[(b,q)]
    if (unit == 0) {
        float* T0 = sa + PA_T0;
        #pragma unroll
        for (int r = 0; r < 8; r++) {
            *(float4*)(T0 + (jb + r) * 68 + mb)     = make_float4(accR[r][0], accR[r][1], accR[r][2], accR[r][3]);
            *(float4*)(T0 + (jb + r) * 68 + mb + 4) = make_float4(accR[r][4], accR[r][5], accR[r][6], accR[r][7]);
        }
    }
    __syncthreads();
    if (unit == 1) {
        const float* T0 = sa + PA_T0;
        float* op = g_accp0 + (size_t)blockIdx.x * 4096;
        #pragma unroll
        for (int r = 0; r < 8; r++) {
            float4 p0 = *(const float4*)(T0 + (jb + r) * 68 + mb);
            float4 p1 = *(const float4*)(T0 + (jb + r) * 68 + mb + 4);
            *(float4*)(op + (jb + r) * 64 + mb) =
                make_float4(p0.x + accR[r][0], p0.y + accR[r][1], p0.z + accR[r][2], p0.w + accR[r][3]);
            *(float4*)(op + (jb + r) * 64 + mb + 4) =
                make_float4(p1.x + accR[r][4], p1.y + accR[r][5], p1.z + accR[r][6], p1.w + accR[r][7]);
        }
    }
}

// ---- agg layer 0: hv1 = hv0 + (sum accp0)*inv @ ew2_0 + eb2_0 ; pre1 ----
__global__ void __launch_bounds__(256)
k_agg0(const float* __restrict__ ew2_0, const float* __restrict__ eb2_0,
       const float* __restrict__ vw1hv1, const float* __restrict__ vb1_1)
{
    extern __shared__ float gsm[];
    float* sA = gsm; float* sW = gsm + 4096; float* sH = gsm + 8192;
    const int b = blockIdx.x, tid = threadIdx.x;
    for (int t = tid; t < 4096; t += 256) {
        sA[t] = (g_accp0[(size_t)(b * 4 + 0) * 4096 + t]
               + g_accp0[(size_t)(b * 4 + 1) * 4096 + t])
              + (g_accp0[(size_t)(b * 4 + 2) * 4096 + t]
               + g_accp0[(size_t)(b * 4 + 3) * 4096 + t]);
        sW[t] = ew2_0[t];
        sH[t] = g_hv[b * 4096 + t];
    }
    __syncthreads();
    mm64(sA, 64, sW, eb2_0, sH, 64, 0, 1.0f / 63.0f, true, tid);
    __syncthreads();
    for (int t = tid; t < 4096; t += 256) { g_hv[b * 4096 + t] = sH[t]; sW[t] = vw1hv1[t]; }
    __syncthreads();
    mm64(sH, 64, sW, vb1_1, sA, 64, 0, 1.f, false, tid);
    __syncthreads();
    for (int t = tid; t < 4096; t += 256) g_pre[b * 4096 + t] = sA[t];
}

// ---- pass B: hidden1 -> gv1 (masked acc), (b,quarter), double-buffered T ----
#define PB_T0   0        // 2 units x 2 bufs x [64][68]
#define PB_WC   17408
#define PB_WD   21504
#define PB_PRE  25600    // [16][64]
#define PB_BFC  26624
#define PB_BD   26688
#define PB_FLOATS 26752
#define PB_BYTES (PB_FLOATS * 4)

__global__ void __launch_bounds__(128, 2)
k_passB()
{
    extern __shared__ float sbm[];
    const int tid = threadIdx.x;
    const int unit = tid >> 6, t64 = tid & 63;
    const int mb = (t64 & 7) * 8, jb = (t64 >> 3) * 8;
    const int b = blockIdx.x >> 2, q = blockIdx.x & 3;
    float* Tbase = sbm + PB_T0 + unit * 8704;   // 2 bufs of 4352
    float* WC   = sbm + PB_WC;
    float* WD   = sbm + PB_WD;
    float* PRE  = sbm + PB_PRE;
    float* BFC  = sbm + PB_BFC;
    float* BD   = sbm + PB_BD;

    for (int t = tid; t < 4096; t += 128) { WC[t] = g_Wf[8192 + t]; WD[t] = g_Wf[12288 + t]; }
    for (int t = tid; t < 1024; t += 128) PRE[t] = g_pre[b * 4096 + q * 1024 + t];
    if (tid < 64) { BFC[tid] = g_bf[128 + tid]; BD[tid] = g_bf[192 + tid]; }
    __syncthreads();

    float accR[8][8] = {};
    float badd[8];
    for (int iq = 0; iq < 8; iq++) {
        const int il = iq * 2 + unit;
        const int i = q * 16 + il;
        float* T = Tbase + (iq & 1) * 4352;
        const float* Ab = g_hid0 + (size_t)(b * 64 + i) * 4096;
        // hidden1 = gelu(hidden0 @ W_C + bC + pre1[i]) -> T (post-sync only)
        #pragma unroll
        for (int u = 0; u < 8; u++) badd[u] = PRE[il * 64 + mb + u] + BFC[mb + u];
        tile_gemm<0, 0>(Ab, 64, WC, jb, mb, badd, T, 0, 0, -1);
        // gv1 = gelu(hidden1 @ W_D + bD), masked acc
        #pragma unroll
        for (int u = 0; u < 8; u++) badd[u] = BD[mb + u];
        tile_gemm<1, 0>(T, 68, WD, jb, mb, badd, 0, 0, accR, i);
    }
    __syncthreads();
    if (unit == 0) {
        float* T0 = sbm + PB_T0;
        #pragma unroll
        for (int r = 0; r < 8; r++) {
            *(float4*)(T0 + (jb + r) * 68 + mb)     = make_float4(accR[r][0], accR[r][1], accR[r][2], accR[r][3]);
            *(float4*)(T0 + (jb + r) * 68 + mb + 4) = make_float4(accR[r][4], accR[r][5], accR[r][6], accR[r][7]);
        }
    }
    __syncthreads();
    if (unit == 1) {
        const float* T0 = sbm + PB_T0;
        float* op = g_accp1 + (size_t)blockIdx.x * 4096;
        #pragma unroll
        for (int r = 0; r < 8; r++) {
            float4 p0 = *(const float4*)(T0 + (jb + r) * 68 + mb);
            float4 p1 = *(const float4*)(T0 + (jb + r) * 68 + mb + 4);
            *(float4*)(op + (jb + r) * 64 + mb) =
                make_float4(p0.x + accR[r][0], p0.y + accR[r][1], p0.z + accR[r][2], p0.w + accR[r][3]);
            *(float4*)(op + (jb + r) * 64 + mb + 4) =
                make_float4(p1.x + accR[r][4], p1.y + accR[r][5], p1.z + accR[r][6], p1.w + accR[r][7]);
        }
    }
}

// ---- final: layer-1 aggregation -> hv2 -> head ----
__global__ void __launch_bounds__(256)
k_final(const float* __restrict__ ew2_1, const float* __restrict__ eb2_1,
        const float* __restrict__ hw1, const float* __restrict__ hb1,
        const float* __restrict__ hw2, const float* __restrict__ hb2,
        const float* __restrict__ scale, float* __restrict__ out)
{
    extern __shared__ float fsm[];
    float* sA = fsm; float* sW = fsm + 4096; float* sH = fsm + 8192;
    float* sT = fsm + 12288; float* sdx = fsm + 16384; float* smn = fsm + 16512;
    const int b = blockIdx.x, tid = threadIdx.x;
    const float inv = 1.0f / 63.0f;

    for (int t = tid; t < 4096; t += 256) {
        sA[t] = (g_accp1[(size_t)(b * 4 + 0) * 4096 + t]
               + g_accp1[(size_t)(b * 4 + 1) * 4096 + t])
              + (g_accp1[(size_t)(b * 4 + 2) * 4096 + t]
               + g_accp1[(size_t)(b * 4 + 3) * 4096 + t]);
        sW[t] = ew2_1[t];
        sH[t] = g_hv[b * 4096 + t];
    }
    __syncthreads();
    mm64(sA, 64, sW, eb2_1, sH, 64, 0, inv, true, tid);   // hv2
    __syncthreads();
    for (int t = tid; t < 4096; t += 256) sW[t] = hw1[t];
    __syncthreads();
    mm64(sH, 64, sW, hb1, sT, 64, 2, 1.f, false, tid);    // tanh hidden
    __syncthreads();
    if (tid < 128) {
        int j = tid >> 1, d = tid & 1;
        float sp = log1pf(expf(scale[0]));
        float s = hb2[d];
        const float* a = sT + j * 64;
        #pragma unroll
        for (int k = 0; k < 64; k++) s = fmaf(a[k], hw2[k * 2 + d], s);
        sdx[tid] = s * sp;
    }
    __syncthreads();
    if (tid < 2) {
        float s = 0.f;
        #pragma unroll
        for (int j = 0; j < 64; j++) s += sdx[j * 2 + tid];
        smn[tid] = s * (1.0f / 64.0f);
    }
    __syncthreads();
    if (tid < 128) out[b * 128 + tid] = sdx[tid] - smn[tid & 1];
}

extern "C" void kernel_launch(void* const* d_in, const int* in_sizes, int n_in,
                              void* d_out, int out_size) {
    (void)out_size;
    const float* ptr[23];
    bool dict_order = (n_in >= 23 && in_sizes[0] == 16384 && in_sizes[2] == 192);
    if (dict_order) {
        for (int i = 0; i < 23; i++) ptr[i] = (const float*)d_in[i];
    } else {
        static const int alpha_to_dict[23] = {
            15, 17, 14, 16,  7,  9,  6,  8, 19, 21, 18, 20,
             3,  5,  2,  4, 22,  1, 11, 13, 10, 12,  0
        };
        for (int i = 0; i < 23; i++) ptr[alpha_to_dict[i]] = (const float*)d_in[i];
    }
    float* out = (float*)d_out;

    const size_t SZ_NODE = 12672u * 4u;
    const size_t SZ_AGG  = 12288u * 4u;
    const size_t SZ_FIN  = 16516u * 4u;
    cudaFuncSetAttribute(k_passA, cudaFuncAttributeMaxDynamicSharedMemorySize, PA_BYTES);
    cudaFuncSetAttribute(k_passB, cudaFuncAttributeMaxDynamicSharedMemorySize, PB_BYTES);
    cudaFuncSetAttribute(k_node,  cudaFuncAttributeMaxDynamicSharedMemorySize, (int)SZ_NODE);
    cudaFuncSetAttribute(k_agg0,  cudaFuncAttributeMaxDynamicSharedMemorySize, (int)SZ_AGG);
    cudaFuncSetAttribute(k_final, cudaFuncAttributeMaxDynamicSharedMemorySize, (int)SZ_FIN);

    // fused weight products W_A..W_D + bias rows
    k_wfuse<<<4, 256>>>(ptr[8], ptr[9], ptr[10], ptr[12], ptr[13], ptr[14], ptr[15]);
    // node MLP -> hv0, pre0
    k_node<<<128, 256, SZ_NODE>>>(ptr[0], ptr[1], ptr[2], ptr[3], ptr[4], ptr[5],
                                  ptr[10], ptr[11]);
    // pass A: hidden0 + gv0 accumulation (512 quarter-CTAs)
    k_passA<<<512, 128, PA_BYTES>>>(ptr[0], ptr[6], ptr[7]);
    // layer-0 aggregation -> hv1, pre1
    k_agg0<<<128, 256, SZ_AGG>>>(ptr[16], ptr[17], ptr[10] + 8192, ptr[11] + 64);
    // pass B: hidden1 + gv1 accumulation (512 quarter-CTAs)
    k_passB<<<512, 128, PB_BYTES>>>();
    // layer-1 aggregation + head
    k_final<<<128, 256, SZ_FIN>>>(ptr[16] + 4096, ptr[17] + 64, ptr[18], ptr[19],
                                  ptr[20], ptr[21], ptr[22], out);
}

// round 17
// speedup vs baseline: 1.0606x; 1.0606x over previous
#include <cuda_runtime.h>
#include <math.h>
#include <stdint.h>

// BackflowNet: B=128, N=64, D=2, H=64, M=64, L=2.
// R17 = R15 + smem bank-conflict elimination in the pass GEMMs:
//   - activation tiles XOR-swizzled (phys quad = q ^ ((j>>3)&3)) -> A-reads conflict-free
//   - W stored with even/odd quad split (wlo @ mb>>1, whi @ +32)  -> W-reads conflict-free
//   k_wfuse -> k_node -> k_passA(256) -> k_agg0(128) -> k_passB(256) -> k_final(128)

__device__ float g_hid0[128u*64u*64u*64u];  // [b][i][j][m] hidden0 (post-gelu), linear
__device__ float g_hv [128u*64u*64u];
__device__ float g_pre[128u*64u*64u];
__device__ float g_accp0[256u*4096u];
__device__ float g_accp1[256u*4096u];
__device__ float g_Wf[4*4096];              // W_A..W_D fused products (linear)
__device__ float g_bf[4*64];

__device__ __forceinline__ float gelu_exact(float x) {
    return 0.5f * x * (1.0f + erff(x * 0.70710678118654752f));
}
__device__ __forceinline__ unsigned long long pk2(float lo, float hi) {
    unsigned long long r;
    asm("mov.b64 %0, {%1, %2};" : "=l"(r) : "f"(lo), "f"(hi));
    return r;
}
__device__ __forceinline__ void upk2(unsigned long long v, float& lo, float& hi) {
    asm("mov.b64 {%0, %1}, %2;" : "=f"(lo), "=f"(hi) : "l"(v));
}
__device__ __forceinline__ void fma2(unsigned long long& d, unsigned long long a, unsigned long long b) {
    asm("fma.rn.f32x2 %0, %1, %2, %0;" : "+l"(d) : "l"(a), "l"(b));
}
// W column permutation: even quads -> 0..7, odd quads -> 8..15
__device__ __forceinline__ int wperm(int m) {
    int q = m >> 2;
    int p = (q >> 1) | ((q & 1) << 3);
    return (p << 2) | (m & 3);
}

#define RANK1(rr, av, wv) \
    rr[0]=fmaf(av, wv.x, rr[0]); rr[1]=fmaf(av, wv.y, rr[1]); \
    rr[2]=fmaf(av, wv.z, rr[2]); rr[3]=fmaf(av, wv.w, rr[3]);
#define TILE4(R, a0v, a1v, a2v, a3v, W) \
    RANK1(R[0], a0v, W) RANK1(R[1], a1v, W) RANK1(R[2], a2v, W) RANK1(R[3], a3v, W)

// scalar 64x64x64 GEMM (256 threads) for small per-batch stages (linear layouts)
__device__ __forceinline__ void mm64(
    const float* __restrict__ in, int istride,
    const float* __restrict__ w, const float* __restrict__ bias,
    float* __restrict__ out, int ostride,
    int act, float inscale, bool accum, int tid)
{
    const int mb = (tid & 15) * 4;
    const int jb = (tid >> 4) * 4;
    const float* i0 = in + jb * istride;
    const float* i1 = i0 + istride;
    const float* i2 = i1 + istride;
    const float* i3 = i2 + istride;
    float r[4][4] = {};
    #pragma unroll 4
    for (int k = 0; k < 64; k += 4) {
        float4 w0 = *(const float4*)(w + (k + 0) * 64 + mb);
        float4 w1 = *(const float4*)(w + (k + 1) * 64 + mb);
        float4 w2 = *(const float4*)(w + (k + 2) * 64 + mb);
        float4 w3 = *(const float4*)(w + (k + 3) * 64 + mb);
        float4 a0 = *(const float4*)(i0 + k);
        float4 a1 = *(const float4*)(i1 + k);
        float4 a2 = *(const float4*)(i2 + k);
        float4 a3 = *(const float4*)(i3 + k);
        TILE4(r, a0.x, a1.x, a2.x, a3.x, w0)
        TILE4(r, a0.y, a1.y, a2.y, a3.y, w1)
        TILE4(r, a0.z, a1.z, a2.z, a3.z, w2)
        TILE4(r, a0.w, a1.w, a2.w, a3.w, w3)
    }
    #pragma unroll
    for (int u = 0; u < 4; u++) {
        float badd = bias ? bias[mb + u] : 0.f;
        #pragma unroll
        for (int v = 0; v < 4; v++) {
            float val = fmaf(r[v][u], inscale, badd);
            if (act == 1) val = gelu_exact(val);
            else if (act == 2) val = tanhf(val);
            float* o = out + (jb + v) * ostride + mb + u;
            if (accum) *o += val; else *o = val;
        }
    }
}

// 64x64x64 f32x2 GEMM tile, 64 threads, 8x8/thread, gelu epilogue.
// W layout: permuted (wperm). A tile: XOR-swizzled smem (SWIZA=1) or linear (SWIZA=0).
// MODE 0: [pre-sync if PRESYNC]; write outT swizzled [+gout linear stride 64]; post-sync.
// MODE 1: masked accumulate into accR (row jb+r != maski), no syncs.
template<int MODE, int PRESYNC, int SWIZA>
__device__ __forceinline__ void tile_gemm(
    const float* Ab, int astr, const float* __restrict__ Ws,
    int jb, int mb, const float badd[8],
    float* outT, float* gout, float (*accR)[8], int maski, int g)
{
    unsigned long long A[8][4];
    #pragma unroll
    for (int r = 0; r < 8; r++)
        #pragma unroll
        for (int p = 0; p < 4; p++) A[r][p] = 0ull;
    const float* base = Ab + jb * astr;
    const int mh = mb >> 1;    // permuted W offset for wlo
    #pragma unroll 2
    for (int k4 = 0; k4 < 16; k4++) {
        const int ac = SWIZA ? ((k4 ^ g) << 2) : (k4 << 2);
        float4 av[8];
        #pragma unroll
        for (int r = 0; r < 8; r++) av[r] = *(const float4*)(base + r * astr + ac);
        #pragma unroll
        for (int kk = 0; kk < 4; kk++) {
            const float* Wrow = Ws + (k4 * 4 + kk) * 64;
            ulonglong2 wlo = *(const ulonglong2*)(Wrow + mh);
            ulonglong2 whi = *(const ulonglong2*)(Wrow + 32 + mh);
            #pragma unroll
            for (int r = 0; r < 8; r++) {
                float a = (kk == 0) ? av[r].x : (kk == 1) ? av[r].y
                        : (kk == 2) ? av[r].z : av[r].w;
                unsigned long long ab = pk2(a, a);
                fma2(A[r][0], ab, wlo.x);
                fma2(A[r][1], ab, wlo.y);
                fma2(A[r][2], ab, whi.x);
                fma2(A[r][3], ab, whi.y);
            }
        }
    }
    if (MODE == 0) {
        if (PRESYNC) __syncthreads();
        const int p0 = (((mb >> 2) ^ g) << 2);         // phys offset of quad mb/4
        const int p1 = ((((mb >> 2) + 1) ^ g) << 2);   // phys offset of quad mb/4+1
        #pragma unroll
        for (int r = 0; r < 8; r++) {
            float o[8];
            #pragma unroll
            for (int p = 0; p < 4; p++) {
                float lo, hi;
                upk2(A[r][p], lo, hi);
                o[2 * p]     = gelu_exact(lo + badd[2 * p]);
                o[2 * p + 1] = gelu_exact(hi + badd[2 * p + 1]);
            }
            float4 lo4 = make_float4(o[0], o[1], o[2], o[3]);
            float4 hi4 = make_float4(o[4], o[5], o[6], o[7]);
            *(float4*)(outT + (jb + r) * 68 + p0) = lo4;
            *(float4*)(outT + (jb + r) * 68 + p1) = hi4;
            if (gout) {
                *(float4*)(gout + (jb + r) * 64 + mb)     = lo4;
                *(float4*)(gout + (jb + r) * 64 + mb + 4) = hi4;
            }
        }
        __syncthreads();
    } else {
        #pragma unroll
        for (int r = 0; r < 8; r++) {
            if (jb + r != maski) {
                #pragma unroll
                for (int p = 0; p < 4; p++) {
                    float lo, hi;
                    upk2(A[r][p], lo, hi);
                    accR[r][2 * p]     += gelu_exact(lo + badd[2 * p]);
                    accR[r][2 * p + 1] += gelu_exact(hi + badd[2 * p + 1]);
                }
            }
        }
    }
}

// ---- fused weight products (linear output) ----
__global__ void __launch_bounds__(256)
k_wfuse(const float* __restrict__ ew2, const float* __restrict__ eb2,
        const float* __restrict__ vw1, const float* __restrict__ vw2,
        const float* __restrict__ vb2,
        const float* __restrict__ cw1, const float* __restrict__ cb1)
{
    __shared__ float sL[4096], sR[4096];
    const int s = blockIdx.x, tid = threadIdx.x;
    const float *L, *R, *bL, *extra = 0;
    if (s == 0)      { L = ew2;        R = vw1 + 4096;         bL = eb2; }
    else if (s == 1) { L = vw2;        R = cw1;                bL = vb2; extra = cb1; }
    else if (s == 2) { L = vw2;        R = vw1 + 8192 + 4096;  bL = vb2; }
    else             { L = vw2 + 4096; R = cw1 + 4096;         bL = vb2 + 64; extra = cb1 + 64; }
    for (int t = tid; t < 4096; t += 256) { sL[t] = L[t]; sR[t] = R[t]; }
    __syncthreads();
    mm64(sL, 64, sR, 0, g_Wf + s * 4096, 64, 0, 1.f, false, tid);
    if (tid < 64) {
        float acc = extra ? extra[tid] : 0.f;
        #pragma unroll 4
        for (int k = 0; k < 64; k++) acc = fmaf(bL[k], sR[k * 64 + tid], acc);
        g_bf[s * 64 + tid] = acc;
    }
}

// ---- node MLP: hv0 + pre0 ----
__global__ void __launch_bounds__(256)
k_node(const float* __restrict__ x, const float* __restrict__ spin,
       const float* __restrict__ nw1, const float* __restrict__ nb1,
       const float* __restrict__ nw2, const float* __restrict__ nb2,
       const float* __restrict__ vw1, const float* __restrict__ vb1)
{
    extern __shared__ float nsm[];
    float* sW = nsm; float* sA = nsm + 4096; float* sB = nsm + 8192;
    float* sxs = nsm + 12288; float* ssp = nsm + 12416; float* sw1 = nsm + 12480;
    const int b = blockIdx.x, tid = threadIdx.x;
    if (tid < 128) sxs[tid] = x[b * 128 + tid];
    if (tid < 64)  ssp[tid] = spin[b * 64 + tid];
    if (tid < 192) sw1[tid] = nw1[tid];
    for (int t = tid; t < 4096; t += 256) sW[t] = nw2[t];
    __syncthreads();
    for (int t = tid; t < 4096; t += 256) {
        int i = t >> 6, h = t & 63;
        float v = fmaf(sxs[i * 2], sw1[h],
                  fmaf(sxs[i * 2 + 1], sw1[64 + h],
                  fmaf(ssp[i], sw1[128 + h], nb1[h])));
        sA[t] = gelu_exact(v);
    }
    __syncthreads();
    mm64(sA, 64, sW, nb2, sB, 64, 0, 1.f, false, tid);   // hv0
    __syncthreads();
    for (int t = tid; t < 4096; t += 256) { g_hv[b * 4096 + t] = sB[t]; sW[t] = vw1[t]; }
    __syncthreads();
    mm64(sB, 64, sW, vb1, sA, 64, 0, 1.f, false, tid);   // pre0
    __syncthreads();
    for (int t = tid; t < 4096; t += 256) g_pre[b * 4096 + t] = sA[t];
}

// ---- pass A: edgeMLP -> hidden0 (store) -> gv0 (masked acc) ----
#define PA_T0   0        // 2 x [64][68] (swizzled)
#define PA_WA   8704
#define PA_WB   12800
#define PA_PRE  16896    // [32][64]
#define PA_F4   18944    // [2][64][4]
#define PA_XS   19456
#define PA_EW1  19584    // [4][64]
#define PA_BEB1 19840
#define PA_BFA  19904
#define PA_BB   19968
#define PA_FLOATS 20032
#define PA_BYTES (PA_FLOATS * 4)

__global__ void __launch_bounds__(128, 2)
k_passA(const float* __restrict__ x, const float* __restrict__ ew1,
        const float* __restrict__ eb1)
{
    extern __shared__ float sa[];
    const int tid = threadIdx.x;
    const int unit = tid >> 6, t64 = tid & 63;
    const int mb = (t64 & 7) * 8, jb = (t64 >> 3) * 8;
    const int g = (t64 >> 3) & 3;
    const int b = blockIdx.x >> 1, half = blockIdx.x & 1;
    float* T    = sa + PA_T0 + unit * 4352;
    float* WA   = sa + PA_WA;
    float* WB   = sa + PA_WB;
    float* PRE  = sa + PA_PRE;
    float* F4u  = sa + PA_F4 + unit * 256;
    float* XS   = sa + PA_XS;
    float* EW1  = sa + PA_EW1;
    float* BEB1 = sa + PA_BEB1;
    float* BFA  = sa + PA_BFA;
    float* BB   = sa + PA_BB;

    for (int t = tid; t < 4096; t += 128) {
        int krow = t >> 6, m = t & 63, d = krow * 64 + wperm(m);
        WA[d] = g_Wf[t]; WB[d] = g_Wf[4096 + t];
    }
    for (int t = tid; t < 2048; t += 128) PRE[t] = g_pre[b * 4096 + half * 2048 + t];
    if (tid < 128) XS[tid] = x[b * 128 + tid];
    if (tid < 64) {
        EW1[tid] = ew1[tid]; EW1[64 + tid] = ew1[64 + tid];
        EW1[128 + tid] = ew1[128 + tid]; EW1[192 + tid] = ew1[192 + tid];
        BEB1[tid] = eb1[tid]; BFA[tid] = g_bf[tid]; BB[tid] = g_bf[64 + tid];
    }
    __syncthreads();

    float accR[8][8] = {};
    float badd[8];
    for (int iq = 0; iq < 16; iq++) {
        const int il = iq * 2 + unit;
        const int i = half * 32 + il;
        {   // geometry for this unit's source row
            int j = t64;
            float d0 = XS[j * 2]     - XS[i * 2];
            float d1 = XS[j * 2 + 1] - XS[i * 2 + 1];
            float r2 = d0 * d0 + d1 * d1;
            float rr = sqrtf(r2 + 1e-12f);
            *(float4*)(F4u + j * 4) = make_float4(d0, d1, rr, r2);
        }
        // also guards prior-iq gv0 readers of T before edge overwrite
        __syncthreads();
        {   // edge MLP hidden: thread owns column m, swizzled store
            int m = t64;
            float w0 = EW1[m], w1 = EW1[64 + m], w2 = EW1[128 + m], w3 = EW1[192 + m];
            float bb = BEB1[m];
            int qm = m >> 2, mm = m & 3;
            #pragma unroll 4
            for (int j = 0; j < 64; j++) {
                const float* f = F4u + j * 4;
                float v = fmaf(f[0], w0, fmaf(f[1], w1, fmaf(f[2], w2, fmaf(f[3], w3, bb))));
                int gj = (j >> 3) & 3;
                T[j * 68 + (((qm ^ gj) << 2) | mm)] = gelu_exact(v);
            }
        }
        __syncthreads();
        // hidden0 = gelu(edge_hidden @ W_A + bA + pre0[i])  [mirror to global, linear]
        #pragma unroll
        for (int u = 0; u < 8; u++) badd[u] = PRE[il * 64 + mb + u] + BFA[mb + u];
        tile_gemm<0, 1, 1>(T, 68, WA, jb, mb, badd, T,
                           g_hid0 + (size_t)(b * 64 + i) * 4096, 0, -1, g);
        // gv0 = gelu(hidden0 @ W_B + bB), masked acc
        #pragma unroll
        for (int u = 0; u < 8; u++) badd[u] = BB[mb + u];
        tile_gemm<1, 0, 1>(T, 68, WB, jb, mb, badd, 0, 0, accR, i, g);
    }
    __syncthreads();
    // combine unit accumulators -> g_accp0[(b,half)]  (linear T0 exchange)
    if (unit == 0) {
        float* T0 = sa + PA_T0;
        #pragma unroll
        for (int r = 0; r < 8; r++) {
            *(float4*)(T0 + (jb + r) * 68 + mb)     = make_float4(accR[r][0], accR[r][1], accR[r][2], accR[r][3]);
            *(float4*)(T0 + (jb + r) * 68 + mb + 4) = make_float4(accR[r][4], accR[r][5], accR[r][6], accR[r][7]);
        }
    }
    __syncthreads();
    if (unit == 1) {
        const float* T0 = sa + PA_T0;
        float* op = g_accp0 + (size_t)blockIdx.x * 4096;
        #pragma unroll
        for (int r = 0; r < 8; r++) {
            float4 p0 = *(const float4*)(T0 + (jb + r) * 68 + mb);
            float4 p1 = *(const float4*)(T0 + (jb + r) * 68 + mb + 4);
            *(float4*)(op + (jb + r) * 64 + mb) =
                make_float4(p0.x + accR[r][0], p0.y + accR[r][1], p0.z + accR[r][2], p0.w + accR[r][3]);
            *(float4*)(op + (jb + r) * 64 + mb + 4) =
                make_float4(p1.x + accR[r][4], p1.y + accR[r][5], p1.z + accR[r][6], p1.w + accR[r][7]);
        }
    }
}

// ---- agg layer 0: hv1 and pre1 ----
__global__ void __launch_bounds__(256)
k_agg0(const float* __restrict__ ew2_0, const float* __restrict__ eb2_0,
       const float* __restrict__ vw1hv1, const float* __restrict__ vb1_1)
{
    extern __shared__ float gsm[];
    float* sA = gsm; float* sW = gsm + 4096; float* sH = gsm + 8192;
    const int b = blockIdx.x, tid = threadIdx.x;
    for (int t = tid; t < 4096; t += 256) {
        sA[t] = g_accp0[(size_t)(b * 2) * 4096 + t]
              + g_accp0[(size_t)(b * 2 + 1) * 4096 + t];
        sW[t] = ew2_0[t];
        sH[t] = g_hv[b * 4096 + t];
    }
    __syncthreads();
    mm64(sA, 64, sW, eb2_0, sH, 64, 0, 1.0f / 63.0f, true, tid);
    __syncthreads();
    for (int t = tid; t < 4096; t += 256) { g_hv[b * 4096 + t] = sH[t]; sW[t] = vw1hv1[t]; }
    __syncthreads();
    mm64(sH, 64, sW, vb1_1, sA, 64, 0, 1.f, false, tid);
    __syncthreads();
    for (int t = tid; t < 4096; t += 256) g_pre[b * 4096 + t] = sA[t];
}

// ---- pass B: hidden1 = gelu(hidden0 @ W_C + pre1) -> gv1, double-buffered T ----
#define PB_T0   0        // 2 units x 2 bufs x [64][68] (swizzled)
#define PB_WC   17408
#define PB_WD   21504
#define PB_PRE  25600    // [32][64]
#define PB_BFC  27648
#define PB_BD   27712
#define PB_FLOATS 27776
#define PB_BYTES (PB_FLOATS * 4)

__global__ void __launch_bounds__(128, 2)
k_passB()
{
    extern __shared__ float sbm[];
    const int tid = threadIdx.x;
    const int unit = tid >> 6, t64 = tid & 63;
    const int mb = (t64 & 7) * 8, jb = (t64 >> 3) * 8;
    const int g = (t64 >> 3) & 3;
    const int b = blockIdx.x >> 1, half = blockIdx.x & 1;
    float* Tbase = sbm + PB_T0 + unit * 8704;
    float* WC   = sbm + PB_WC;
    float* WD   = sbm + PB_WD;
    float* PRE  = sbm + PB_PRE;
    float* BFC  = sbm + PB_BFC;
    float* BD   = sbm + PB_BD;

    for (int t = tid; t < 4096; t += 128) {
        int krow = t >> 6, m = t & 63, d = krow * 64 + wperm(m);
        WC[d] = g_Wf[8192 + t]; WD[d] = g_Wf[12288 + t];
    }
    for (int t = tid; t < 2048; t += 128) PRE[t] = g_pre[b * 4096 + half * 2048 + t];
    if (tid < 64) { BFC[tid] = g_bf[128 + tid]; BD[tid] = g_bf[192 + tid]; }
    __syncthreads();

    float accR[8][8] = {};
    float badd[8];
    for (int iq = 0; iq < 16; iq++) {
        const int il = iq * 2 + unit;
        const int i = half * 32 + il;
        float* T = Tbase + (iq & 1) * 4352;
        const float* Ab = g_hid0 + (size_t)(b * 64 + i) * 4096;
        // hidden1 = gelu(hidden0 @ W_C + bC + pre1[i]) -> T (A linear, writes swizzled)
        #pragma unroll
        for (int u = 0; u < 8; u++) badd[u] = PRE[il * 64 + mb + u] + BFC[mb + u];
        tile_gemm<0, 0, 0>(Ab, 64, WC, jb, mb, badd, T, 0, 0, -1, g);
        // gv1 = gelu(hidden1 @ W_D + bD), masked acc (reads swizzled)
        #pragma unroll
        for (int u = 0; u < 8; u++) badd[u] = BD[mb + u];
        tile_gemm<1, 0, 1>(T, 68, WD, jb, mb, badd, 0, 0, accR, i, g);
    }
    __syncthreads();
    if (unit == 0) {
        float* T0 = sbm + PB_T0;
        #pragma unroll
        for (int r = 0; r < 8; r++) {
            *(float4*)(T0 + (jb + r) * 68 + mb)     = make_float4(accR[r][0], accR[r][1], accR[r][2], accR[r][3]);
            *(float4*)(T0 + (jb + r) * 68 + mb + 4) = make_float4(accR[r][4], accR[r][5], accR[r][6], accR[r][7]);
        }
    }
    __syncthreads();
    if (unit == 1) {
        const float* T0 = sbm + PB_T0;
        float* op = g_accp1 + (size_t)blockIdx.x * 4096;
        #pragma unroll
        for (int r = 0; r < 8; r++) {
            float4 p0 = *(const float4*)(T0 + (jb + r) * 68 + mb);
            float4 p1 = *(const float4*)(T0 + (jb + r) * 68 + mb + 4);
            *(float4*)(op + (jb + r) * 64 + mb) =
                make_float4(p0.x + accR[r][0], p0.y + accR[r][1], p0.z + accR[r][2], p0.w + accR[r][3]);
            *(float4*)(op + (jb + r) * 64 + mb + 4) =
                make_float4(p1.x + accR[r][4], p1.y + accR[r][5], p1.z + accR[r][6], p1.w + accR[r][7]);
        }
    }
}

// ---- final: layer-1 aggregation -> hv2 -> head ----
__global__ void __launch_bounds__(256)
k_final(const float* __restrict__ ew2_1, const float* __restrict__ eb2_1,
        const float* __restrict__ hw1, const float* __restrict__ hb1,
        const float* __restrict__ hw2, const float* __restrict__ hb2,
        const float* __restrict__ scale, float* __restrict__ out)
{
    extern __shared__ float fsm[];
    float* sA = fsm; float* sW = fsm + 4096; float* sH = fsm + 8192;
    float* sT = fsm + 12288; float* sdx = fsm + 16384; float* smn = fsm + 16512;
    const int b = blockIdx.x, tid = threadIdx.x;
    const float inv = 1.0f / 63.0f;

    for (int t = tid; t < 4096; t += 256) {
        sA[t] = g_accp1[(size_t)(b * 2) * 4096 + t]
              + g_accp1[(size_t)(b * 2 + 1) * 4096 + t];
        sW[t] = ew2_1[t];
        sH[t] = g_hv[b * 4096 + t];
    }
    __syncthreads();
    mm64(sA, 64, sW, eb2_1, sH, 64, 0, inv, true, tid);   // hv2
    __syncthreads();
    for (int t = tid; t < 4096; t += 256) sW[t] = hw1[t];
    __syncthreads();
    mm64(sH, 64, sW, hb1, sT, 64, 2, 1.f, false, tid);    // tanh hidden
    __syncthreads();
    if (tid < 128) {
        int j = tid >> 1, d = tid & 1;
        float sp = log1pf(expf(scale[0]));
        float s = hb2[d];
        const float* a = sT + j * 64;
        #pragma unroll
        for (int k = 0; k < 64; k++) s = fmaf(a[k], hw2[k * 2 + d], s);
        sdx[tid] = s * sp;
    }
    __syncthreads();
    if (tid < 2) {
        float s = 0.f;
        #pragma unroll
        for (int j = 0; j < 64; j++) s += sdx[j * 2 + tid];
        smn[tid] = s * (1.0f / 64.0f);
    }
    __syncthreads();
    if (tid < 128) out[b * 128 + tid] = sdx[tid] - smn[tid & 1];
}

extern "C" void kernel_launch(void* const* d_in, const int* in_sizes, int n_in,
                              void* d_out, int out_size) {
    (void)out_size;
    const float* ptr[23];
    bool dict_order = (n_in >= 23 && in_sizes[0] == 16384 && in_sizes[2] == 192);
    if (dict_order) {
        for (int i = 0; i < 23; i++) ptr[i] = (const float*)d_in[i];
    } else {
        static const int alpha_to_dict[23] = {
            15, 17, 14, 16,  7,  9,  6,  8, 19, 21, 18, 20,
             3,  5,  2,  4, 22,  1, 11, 13, 10, 12,  0
        };
        for (int i = 0; i < 23; i++) ptr[alpha_to_dict[i]] = (const float*)d_in[i];
    }
    float* out = (float*)d_out;

    const size_t SZ_NODE = 12672u * 4u;
    const size_t SZ_AGG  = 12288u * 4u;
    const size_t SZ_FIN  = 16516u * 4u;
    cudaFuncSetAttribute(k_passA, cudaFuncAttributeMaxDynamicSharedMemorySize, PA_BYTES);
    cudaFuncSetAttribute(k_passB, cudaFuncAttributeMaxDynamicSharedMemorySize, PB_BYTES);
    cudaFuncSetAttribute(k_node,  cudaFuncAttributeMaxDynamicSharedMemorySize, (int)SZ_NODE);
    cudaFuncSetAttribute(k_agg0,  cudaFuncAttributeMaxDynamicSharedMemorySize, (int)SZ_AGG);
    cudaFuncSetAttribute(k_final, cudaFuncAttributeMaxDynamicSharedMemorySize, (int)SZ_FIN);

    k_wfuse<<<4, 256>>>(ptr[8], ptr[9], ptr[10], ptr[12], ptr[13], ptr[14], ptr[15]);
    k_node<<<128, 256, SZ_NODE>>>(ptr[0], ptr[1], ptr[2], ptr[3], ptr[4], ptr[5],
                                  ptr[10], ptr[11]);
    k_passA<<<256, 128, PA_BYTES>>>(ptr[0], ptr[6], ptr[7]);
    k_agg0<<<128, 256, SZ_AGG>>>(ptr[16], ptr[17], ptr[10] + 8192, ptr[11] + 64);
    k_passB<<<256, 128, PB_BYTES>>>();
    k_final<<<128, 256, SZ_FIN>>>(ptr[16] + 4096, ptr[17] + 64, ptr[18], ptr[19],
                                  ptr[20], ptr[21], ptr[22], out);
}